// round 12
// baseline (speedup 1.0000x reference)
#include <cuda_runtime.h>
#include <cuda_fp16.h>
#include <cstdint>

#define NB 4
#define NN 4096
#define LOG2E 1.4426950408889634f

// ---------------- scratch (__device__ globals; no allocation) ----------------
__device__ __align__(256) __half g_Qh[NB * NN * 8];   // [b][n][8], pre-scaled by log2e
__device__ __align__(256) __half g_Kh[NB * NN * 8];   // [b][n][8]
__device__ __align__(256) __half g_Vh[NB * NN * 64];  // [b][n][64]

// ---------------- helpers ----------------
__device__ __forceinline__ uint32_t smem_u32(const void* p) {
    uint32_t a;
    asm("{ .reg .u64 t; cvta.to.shared.u64 t, %1; cvt.u32.u64 %0, t; }" : "=r"(a) : "l"(p));
    return a;
}
__device__ __forceinline__ uint32_t swz128(uint32_t b) { return b ^ ((b >> 3) & 0x70u); }

#define CP_ASYNC16(dst, src) \
    asm volatile("cp.async.cg.shared.global [%0], [%1], 16;" :: "r"(dst), "l"(src) : "memory")
#define CP_COMMIT() asm volatile("cp.async.commit_group;" ::: "memory")
#define CP_WAIT0()  asm volatile("cp.async.wait_group 0;" ::: "memory")
#define CP_WAIT1()  asm volatile("cp.async.wait_group 1;" ::: "memory")

#define LDSM_X2(r0, r1, a) \
    asm volatile("ldmatrix.sync.aligned.m8n8.x2.shared.b16 {%0,%1}, [%2];" \
                 : "=r"(r0), "=r"(r1) : "r"(a))
#define LDSM_X4(r0, r1, r2, r3, a) \
    asm volatile("ldmatrix.sync.aligned.m8n8.x4.shared.b16 {%0,%1,%2,%3}, [%4];" \
                 : "=r"(r0), "=r"(r1), "=r"(r2), "=r"(r3) : "r"(a))
#define LDSM_X4T(r0, r1, r2, r3, a) \
    asm volatile("ldmatrix.sync.aligned.m8n8.x4.trans.shared.b16 {%0,%1,%2,%3}, [%4];" \
                 : "=r"(r0), "=r"(r1), "=r"(r2), "=r"(r3) : "r"(a))

// S(16x8,f16) = Q(16x8,f16) @ K^T ; C = 0
__device__ __forceinline__ void mma16808h(uint32_t* d, uint32_t a0, uint32_t a1, uint32_t b0) {
    uint32_t z = 0;
    asm volatile("mma.sync.aligned.m16n8k8.row.col.f16.f16.f16.f16 "
                 "{%0,%1}, {%2,%3}, {%4}, {%5,%5};"
                 : "=r"(d[0]), "=r"(d[1]) : "r"(a0), "r"(a1), "r"(b0), "r"(z));
}
// O(16x8,f16) += P(16x16,f16) @ V(16x8,f16)
__device__ __forceinline__ void mma16816h(uint32_t* d, const uint32_t* a, uint32_t b0, uint32_t b1) {
    asm volatile("mma.sync.aligned.m16n8k16.row.col.f16.f16.f16.f16 "
                 "{%0,%1}, {%2,%3,%4,%5}, {%6,%7}, {%0,%1};"
                 : "+r"(d[0]), "+r"(d[1])
                 : "r"(a[0]), "r"(a[1]), "r"(a[2]), "r"(a[3]), "r"(b0), "r"(b1));
}
#define EX2H2(r) asm volatile("ex2.approx.f16x2 %0, %0;" : "+r"(r))
__device__ __forceinline__ uint32_t hadd2u(uint32_t a, uint32_t b) {
    uint32_t d; asm("add.rn.f16x2 %0, %1, %2;" : "=r"(d) : "r"(a), "r"(b)); return d;
}
__device__ __forceinline__ float h2sumf(uint32_t r) {
    __half2 h = *reinterpret_cast<__half2*>(&r);
    return __low2float(h) + __high2float(h);
}

// ---------------------------------------------------------------------------
// Kernel 1: fused QKV projections (f16 outputs, staged coalesced stores)
// ---------------------------------------------------------------------------
__global__ __launch_bounds__(256) void prep_kernel(
    const float* __restrict__ x,
    const float* __restrict__ Wq, const float* __restrict__ bq,
    const float* __restrict__ Wk, const float* __restrict__ bk,
    const float* __restrict__ Wv, const float* __restrict__ bv)
{
    __shared__ __align__(16) float xs[64 * 64];
    __shared__ __align__(16) float ws[80 * 64];   // weights; reused as output staging
    __shared__ float bs[80];

    const int t  = threadIdx.x;
    const int b  = blockIdx.y;
    const int n0 = blockIdx.x * 64;

    for (int lin = t; lin < 80 * 64; lin += 256) {
        int o = lin >> 6, c = lin & 63;
        float w;
        if (o < 8)       w = Wq[o * 64 + c] * LOG2E;
        else if (o < 16) w = Wk[(o - 8) * 64 + c];
        else             w = Wv[(o - 16) * 64 + c];
        ws[o * 64 + c] = w;
    }
    if (t < 80) {
        float bb;
        if (t < 8)       bb = bq[t] * LOG2E;
        else if (t < 16) bb = bk[t - 8];
        else             bb = bv[t - 16];
        bs[t] = bb;
    }
    for (int lin = t; lin < 64 * 64; lin += 256) {
        int c = lin >> 6, i = lin & 63;
        xs[c * 64 + i] = x[(b * 64 + c) * NN + n0 + i];
    }
    __syncthreads();

    const int tx = t & 63;
    const int ty = t >> 6;

    float acc[20];
#pragma unroll
    for (int i = 0; i < 20; i++) acc[i] = 0.f;
#pragma unroll
    for (int c = 0; c < 64; c++) {
        float xv = xs[c * 64 + tx];
#pragma unroll
        for (int oo = 0; oo < 20; oo++)
            acc[oo] += ws[(ty * 20 + oo) * 64 + c] * xv;
    }
    float bias[20];
#pragma unroll
    for (int oo = 0; oo < 20; oo++) bias[oo] = bs[ty * 20 + oo];

    __syncthreads();   // done reading ws -> reuse as staging

    char* stage = (char*)ws;
#pragma unroll
    for (int oo = 0; oo < 20; oo++) {
        int o = ty * 20 + oo;
        __half h = __float2half(acc[oo] + bias[oo]);
        if (o < 8)
            *(__half*)(stage + tx * 16 + o * 2) = h;
        else if (o < 16)
            *(__half*)(stage + 1024 + tx * 16 + (o - 8) * 2) = h;
        else
            *(__half*)(stage + 2048 + tx * 136 + (o - 16) * 2) = h;
    }
    __syncthreads();

    if (t < 64) {
        *(uint4*)(g_Qh + ((size_t)b * NN + n0 + t) * 8) = *(const uint4*)(stage + t * 16);
    } else if (t < 128) {
        int i = t - 64;
        *(uint4*)(g_Kh + ((size_t)b * NN + n0 + i) * 8) = *(const uint4*)(stage + 1024 + i * 16);
    }
#pragma unroll
    for (int i = 0; i < 4; i++) {
        int lin = t + i * 256;               // 1024 chunks of 8B
        int pix = lin >> 4, chk = lin & 15;
        *(uint2*)(g_Vh + ((size_t)b * NN + n0 + pix) * 64 + chk * 4) =
            *(const uint2*)(stage + 2048 + pix * 136 + chk * 8);
    }
}

// ---------------------------------------------------------------------------
// Kernel 2: flash attention. CTA = 64 queries, 8 warps; warp kq owns ALL 64
// rows x 16-key slice of each 128-key tile (V frags loaded once per slice).
// 3-stage cp.async pipeline, one barrier/iter, register-chained P.
// ---------------------------------------------------------------------------
#define SM_SQ 0u
#define SM_ST 1024u
#define STAGE 18432u
#define DSMEM_BYTES 56320u
// epilogue layout (reuses stage region):
//   sOp: 4 slots, each [64 rows][36 u32] (u32 = half2 of channels c,c+1)
#define EP_OP   1024u
#define EP_SLOT 9216u           // 64*36*4 bytes
#define EP_L    37888u          // float[8][64]

__global__ __launch_bounds__(256, 2) void attn_kernel(
    const float* __restrict__ x,
    const float* __restrict__ gamma_p,
    float* __restrict__ out)
{
    extern __shared__ __align__(1024) unsigned char dynsm[];

    const int t    = threadIdx.x;
    const int lane = t & 31;
    const int kq   = t >> 5;            // warp = key slice 0..7
    const int b    = blockIdx.y;
    const int q0   = blockIdx.x * 64;

    const uint32_t sb  = smem_u32(dynsm);
    const uint32_t sbQ = sb + SM_SQ;

    // PDL: wait for prep_kernel before touching its outputs
    cudaGridDependencySynchronize();

    // prologue: Q + tiles 0,1 (two commit groups)
    if (t < 64)
        CP_ASYNC16(sbQ + (uint32_t)t * 16u, (const char*)(g_Qh + ((size_t)b * NN + q0 + t) * 8));
    {
        const uint32_t st0 = sb + SM_ST;
        if (t < 128)
            CP_ASYNC16(st0 + (uint32_t)t * 16u, (const char*)(g_Kh + ((size_t)b * NN + t) * 8));
#pragma unroll
        for (int i = 0; i < 4; i++) {
            int cid = t + i * 256;
            int vk = cid >> 3, vc = cid & 7;
            CP_ASYNC16(st0 + 2048u + swz128((uint32_t)vk * 128u + (uint32_t)vc * 16u),
                       (const char*)(g_Vh + ((size_t)b * NN + vk) * 64 + vc * 8));
        }
    }
    CP_COMMIT();
    {
        const uint32_t st1 = sb + SM_ST + STAGE;
        if (t < 128)
            CP_ASYNC16(st1 + (uint32_t)t * 16u, (const char*)(g_Kh + ((size_t)b * NN + 128 + t) * 8));
#pragma unroll
        for (int i = 0; i < 4; i++) {
            int cid = t + i * 256;
            int vk = cid >> 3, vc = cid & 7;
            CP_ASYNC16(st1 + 2048u + swz128((uint32_t)vk * 128u + (uint32_t)vc * 16u),
                       (const char*)(g_Vh + ((size_t)b * NN + 128 + vk) * 64 + vc * 8));
        }
    }
    CP_COMMIT();

    uint32_t o[4][16];                  // [rowfrag][nt*2+d] f16x2 accumulators, 64 rows
#pragma unroll
    for (int rf = 0; rf < 4; rf++)
#pragma unroll
        for (int i = 0; i < 16; i++) o[rf][i] = 0u;
    float lacc[8] = {0.f, 0.f, 0.f, 0.f, 0.f, 0.f, 0.f, 0.f};   // [2rf+d]
    uint32_t qa[8];

    for (int it = 0; it < 32; it++) {
        if (it == 31) { CP_WAIT0(); } else { CP_WAIT1(); }   // tile `it` landed
        __syncthreads();   // all warps done with tile it-1 -> its buffer reusable

        if (it + 2 < 32) {  // prefetch tile it+2 into stage (it+2)%3
            const uint32_t std_ = sb + SM_ST + (uint32_t)((it + 2) % 3) * STAGE;
            const int kbase = (it + 2) * 128;
            if (t < 128)
                CP_ASYNC16(std_ + (uint32_t)t * 16u,
                           (const char*)(g_Kh + ((size_t)b * NN + kbase + t) * 8));
#pragma unroll
            for (int i = 0; i < 4; i++) {
                int cid = t + i * 256;
                int vk = cid >> 3, vc = cid & 7;
                CP_ASYNC16(std_ + 2048u + swz128((uint32_t)vk * 128u + (uint32_t)vc * 16u),
                           (const char*)(g_Vh + ((size_t)b * NN + kbase + vk) * 64 + vc * 8));
            }
            CP_COMMIT();
        }

        if (it == 0) {  // Q A-frags for all 64 rows, resident all loop
            LDSM_X4(qa[0], qa[1], qa[2], qa[3], sbQ + (uint32_t)lane * 16u);
            LDSM_X4(qa[4], qa[5], qa[6], qa[7], sbQ + (uint32_t)(32 + lane) * 16u);
        }

        const uint32_t kbuf = sb + SM_ST + (uint32_t)(it % 3) * STAGE;
        const uint32_t vbuf = kbuf + 2048u;

        // K frag: 16 keys of this slice
        uint32_t kb[2];
        LDSM_X2(kb[0], kb[1], kbuf + (uint32_t)(kq * 16 + (lane & 15)) * 16u);

        // V frags for 16 keys x 64 ch (loaded ONCE per slice)
        uint32_t vb[16];
        {
            const uint32_t vkey = (uint32_t)(kq * 16 + ((lane >> 3) & 1) * 8 + (lane & 7));
#pragma unroll
            for (int ntp = 0; ntp < 4; ntp++) {
                uint32_t cb = (uint32_t)(ntp * 2 + (lane >> 4));
                LDSM_X4T(vb[4 * ntp], vb[4 * ntp + 1], vb[4 * ntp + 2], vb[4 * ntp + 3],
                         vbuf + swz128(vkey * 128u + cb * 16u));
            }
        }

        // MMA1: S(64 rows x 16 keys); s[4rf..] is directly the MMA2 A-frag
        uint32_t s[16];
#pragma unroll
        for (int rf = 0; rf < 4; rf++) {
            mma16808h(s + 4 * rf,     qa[2 * rf], qa[2 * rf + 1], kb[0]);
            mma16808h(s + 4 * rf + 2, qa[2 * rf], qa[2 * rf + 1], kb[1]);
        }

        // exp2 in place
#pragma unroll
        for (int i = 0; i < 16; i++) EX2H2(s[i]);

        // MMA2: O += P @ V
#pragma unroll
        for (int rf = 0; rf < 4; rf++)
#pragma unroll
            for (int nt = 0; nt < 8; nt++)
                mma16816h(&o[rf][2 * nt], s + 4 * rf, vb[2 * nt], vb[2 * nt + 1]);

        // row sums (off critical path)
#pragma unroll
        for (int rf = 0; rf < 4; rf++) {
            lacc[2 * rf]     += h2sumf(hadd2u(s[4 * rf],     s[4 * rf + 2]));
            lacc[2 * rf + 1] += h2sumf(hadd2u(s[4 * rf + 1], s[4 * rf + 3]));
        }
    }

    // ---- epilogue: combine 8 key-slices (two-phase through smem) ----
#pragma unroll
    for (int j = 0; j < 8; j++) {
        lacc[j] += __shfl_xor_sync(0xffffffffu, lacc[j], 1);
        lacc[j] += __shfl_xor_sync(0xffffffffu, lacc[j], 2);
    }
    const float gma = __ldg(gamma_p);

    __syncthreads();            // all loop reads of stages done -> reuse region

    uint32_t* sOp32 = (uint32_t*)(dynsm + EP_OP);   // [slot][row][36 u32]
    float*    sL    = (float*)(dynsm + EP_L);       // [8][64]

    if ((lane & 3) == 0) {
#pragma unroll
        for (int j = 0; j < 8; j++) {
            int row = (j >> 1) * 16 + (j & 1) * 8 + (lane >> 2);
            sL[kq * 64 + row] = lacc[j];
        }
    }

    // pass 1: warps 4-7 stage their partial O
    if (kq >= 4) {
        uint32_t* slotp = sOp32 + (uint32_t)(kq - 4) * (EP_SLOT / 4u);
#pragma unroll
        for (int rf = 0; rf < 4; rf++)
#pragma unroll
            for (int nt = 0; nt < 8; nt++)
#pragma unroll
                for (int d = 0; d < 2; d++) {
                    int row = rf * 16 + d * 8 + (lane >> 2);
                    int cu  = nt * 4 + (lane & 3);
                    slotp[row * 36 + cu] = o[rf][2 * nt + d];
                }
    }
    __syncthreads();

    // pass 2: warps 0-3 add their partials into the slots
    if (kq < 4) {
        uint32_t* slotp = sOp32 + (uint32_t)kq * (EP_SLOT / 4u);
#pragma unroll
        for (int rf = 0; rf < 4; rf++)
#pragma unroll
            for (int nt = 0; nt < 8; nt++)
#pragma unroll
                for (int d = 0; d < 2; d++) {
                    int row = rf * 16 + d * 8 + (lane >> 2);
                    int cu  = nt * 4 + (lane & 3);
                    uint32_t idx = (uint32_t)(row * 36 + cu);
                    slotp[idx] = hadd2u(slotp[idx], o[rf][2 * nt + d]);
                }
    }
    __syncthreads();

    // pass 3: final combine + scale + residual, coalesced per q
    {
        const int q = t & 63;
        float l = 0.f;
#pragma unroll
        for (int s8 = 0; s8 < 8; s8++) l += sL[s8 * 64 + q];
        const float inv = gma / l;
        const __half* sOph = (const __half*)sOp32;   // half idx: slot*4608 + row*72 + c
#pragma unroll
        for (int i = 0; i < 16; i++) {
            int c = (t >> 6) + 4 * i;
            float acc = (float)sOph[0 * 4608 + q * 72 + c] + (float)sOph[1 * 4608 + q * 72 + c]
                      + (float)sOph[2 * 4608 + q * 72 + c] + (float)sOph[3 * 4608 + q * 72 + c];
            size_t idx = ((size_t)b * 64 + c) * NN + q0 + q;
            out[idx] = acc * inv + x[idx];
        }
    }
}

// ---------------------------------------------------------------------------
extern "C" void kernel_launch(void* const* d_in, const int* in_sizes, int n_in,
                              void* d_out, int out_size) {
    (void)in_sizes; (void)n_in; (void)out_size;
    const float* x     = (const float*)d_in[0];
    const float* Wq    = (const float*)d_in[1];
    const float* bq    = (const float*)d_in[2];
    const float* Wk    = (const float*)d_in[3];
    const float* bk    = (const float*)d_in[4];
    const float* Wv    = (const float*)d_in[5];
    const float* bv    = (const float*)d_in[6];
    const float* gamma = (const float*)d_in[7];
    float* out = (float*)d_out;

    cudaFuncSetAttribute(attn_kernel, cudaFuncAttributeMaxDynamicSharedMemorySize,
                         (int)DSMEM_BYTES);

    prep_kernel<<<dim3(64, NB), 256>>>(x, Wq, bq, Wk, bk, Wv, bv);

    // attn with programmatic stream serialization
    cudaLaunchConfig_t cfg = {};
    cfg.gridDim  = dim3(64, NB);
    cfg.blockDim = dim3(256);
    cfg.dynamicSmemBytes = DSMEM_BYTES;
    cfg.stream = 0;
    cudaLaunchAttribute attrs[1];
    attrs[0].id = cudaLaunchAttributeProgrammaticStreamSerialization;
    attrs[0].val.programmaticStreamSerializationAllowed = 1;
    cfg.attrs = attrs;
    cfg.numAttrs = 1;
    cudaLaunchKernelEx(&cfg, attn_kernel, x, gamma, out);
}